// round 12
// baseline (speedup 1.0000x reference)
#include <cuda_runtime.h>

// Problem constants (fixed by the reference)
#define BB 8
#define SS 8192
#define DD 768
#define VV 64
#define LL 26
#define NSEG  (BB * VV)       // 512
#define NHALF (NSEG * 2)      // 1024 CTAs: (segment, D-half)
#define HD    (DD / 2)        // 384 floats per half
#define HD4   (HD / 4)        // 96 float4 lanes
#define NTHR  288             // 3 groups x 96 lanes = 9 warps
#define CAP   2048

// ---------------------------------------------------------------------------
// Kernel 0: zero the output so the halves can accumulate atomically.
__global__ void k_zero_out(float* __restrict__ out) {
    int i = blockIdx.x * blockDim.x + threadIdx.x;
    if (i < NSEG * LL) out[i] = 0.0f;
}

// ---------------------------------------------------------------------------
// Kernel 1: one CTA per (segment, D-half). Balanced grid of 1024.
//  A: int4 scan of the batch's 8192 ids -> smem index list (per-half rescan).
//  B: 3 groups of 96 lanes gather-sum this half of each matching row.
//  C: partial 26-label dot over this D-half; atomicAdd scaled result into out.
__global__ __launch_bounds__(NTHR, 7) void k_gather(
    const float* __restrict__ h,      // [B*S, D]
    const int*   __restrict__ ids,    // [B*S]
    const float* __restrict__ Wm,     // [L, D]
    const float* __restrict__ bias,   // [L]
    float* __restrict__ out)          // [B, V, L]
{
    const int task = blockIdx.x;
    const int seg  = task >> 1;
    const int half = task & 1;
    const int b    = seg >> 6;
    const int v    = seg & (VV - 1);
    const int tid  = threadIdx.x;
    const int grp  = tid / 96;         // 0..2
    const int ln   = tid % 96;         // float4 lane within the half-row

    __shared__ __align__(16) float ssum[3][HD];   // 4.5 KB
    __shared__ int slist[CAP];                    // 8 KB
    __shared__ int scount;

    if (v == 0) return;                // masked: out stays zero from k_zero_out

    if (tid == 0) scount = 0;
    __syncthreads();

    // ---- Phase A: vectorized id scan ----
    {
        const int4* __restrict__ idb4 = (const int4*)(ids + b * SS);
        #pragma unroll
        for (int g = 0; g < 8; ++g) {
            int q = tid + g * NTHR;            // int4 index
            if (q < SS / 4) {
                int4 w = __ldg(&idb4[q]);
                int s = q * 4;
                if (w.x == v) { int p = atomicAdd(&scount, 1); if (p < CAP) slist[p] = s;     }
                if (w.y == v) { int p = atomicAdd(&scount, 1); if (p < CAP) slist[p] = s + 1; }
                if (w.z == v) { int p = atomicAdd(&scount, 1); if (p < CAP) slist[p] = s + 2; }
                if (w.w == v) { int p = atomicAdd(&scount, 1); if (p < CAP) slist[p] = s + 3; }
            }
        }
    }
    __syncthreads();
    const int cnt = (scount < CAP) ? scount : CAP;

    // ---- Phase B: group g sums tokens g, g+3, ... over this D-half ----
    float4 acc = make_float4(0.f, 0.f, 0.f, 0.f);
    {
        const float4* __restrict__ hb =
            (const float4*)h + (long)b * SS * (DD / 4) + half * HD4 + ln;
        int i = grp;
        for (; i + 7 * 3 < cnt; i += 8 * 3) {
            float4 t0 = __ldg(hb + (long)slist[i + 0 * 3] * (DD / 4));
            float4 t1 = __ldg(hb + (long)slist[i + 1 * 3] * (DD / 4));
            float4 t2 = __ldg(hb + (long)slist[i + 2 * 3] * (DD / 4));
            float4 t3 = __ldg(hb + (long)slist[i + 3 * 3] * (DD / 4));
            acc.x += (t0.x + t1.x) + (t2.x + t3.x);
            acc.y += (t0.y + t1.y) + (t2.y + t3.y);
            acc.z += (t0.z + t1.z) + (t2.z + t3.z);
            acc.w += (t0.w + t1.w) + (t2.w + t3.w);
            float4 t4 = __ldg(hb + (long)slist[i + 4 * 3] * (DD / 4));
            float4 t5 = __ldg(hb + (long)slist[i + 5 * 3] * (DD / 4));
            float4 t6 = __ldg(hb + (long)slist[i + 6 * 3] * (DD / 4));
            float4 t7 = __ldg(hb + (long)slist[i + 7 * 3] * (DD / 4));
            acc.x += (t4.x + t5.x) + (t6.x + t7.x);
            acc.y += (t4.y + t5.y) + (t6.y + t7.y);
            acc.z += (t4.z + t5.z) + (t6.z + t7.z);
            acc.w += (t4.w + t5.w) + (t6.w + t7.w);
        }
        for (; i < cnt; i += 3) {
            float4 t = __ldg(hb + (long)slist[i] * (DD / 4));
            acc.x += t.x; acc.y += t.y; acc.z += t.z; acc.w += t.w;
        }
    }
    ((float4*)ssum[grp])[ln] = acc;
    __syncthreads();

    if (cnt == 0) return;              // absent symbol: out stays zero

    // ---- Phase C1: reduce the 3 group partials into ssum[0] ----
    if (tid < HD4) {
        float4 a0 = ((const float4*)ssum[0])[tid];
        float4 a1 = ((const float4*)ssum[1])[tid];
        float4 a2 = ((const float4*)ssum[2])[tid];
        a0.x += a1.x + a2.x;
        a0.y += a1.y + a2.y;
        a0.z += a1.z + a2.z;
        a0.w += a1.w + a2.w;
        ((float4*)ssum[0])[tid] = a0;
    }
    __syncthreads();

    // ---- Phase C2: partial dot over this half; atomic accumulate to out ----
    const int   warp = tid >> 5;       // 0..8
    const int   lane = tid & 31;
    const float inv  = 1.0f / (float)cnt;
    const float* __restrict__ Wh = Wm + half * HD;

    for (int l = warp; l < LL; l += 9) {
        float s = 0.f;
        #pragma unroll
        for (int k = lane; k < HD; k += 32)
            s += ssum[0][k] * __ldg(&Wh[l * DD + k]);
        #pragma unroll
        for (int o = 16; o; o >>= 1)
            s += __shfl_xor_sync(0xffffffffu, s, o);
        if (lane == 0) {
            float r = s * inv + 0.5f * __ldg(&bias[l]);   // each half adds bias/2
            atomicAdd(&out[seg * LL + l], r);
        }
    }
}

// ---------------------------------------------------------------------------
extern "C" void kernel_launch(void* const* d_in, const int* in_sizes, int n_in,
                              void* d_out, int out_size) {
    const float* h    = nullptr;   // 50331648
    const float* Wm   = nullptr;   // 19968
    const float* bias = nullptr;   // 26
    const int*   ids  = nullptr;   // 65536
    for (int i = 0; i < n_in; ++i) {
        switch (in_sizes[i]) {
            case BB * SS * DD: h    = (const float*)d_in[i]; break;
            case LL * DD:      Wm   = (const float*)d_in[i]; break;
            case LL:           bias = (const float*)d_in[i]; break;
            case BB * SS:      ids  = (const int*)d_in[i];   break;
        }
    }
    float* out = (float*)d_out;

    k_zero_out<<<(NSEG * LL + 1023) / 1024, 1024>>>(out);
    k_gather<<<NHALF, NTHR>>>(h, ids, Wm, bias, out);
}